// round 1
// baseline (speedup 1.0000x reference)
#include <cuda_runtime.h>

#define Bb 2
#define Nn 3136
#define Cc 256
#define Hh 56
#define NHEADS 8
#define HD 32

// Scratch (allocation-free): Q, K, V projections and attention output.
__device__ float g_Q[Bb * Nn * Cc];
__device__ float g_K[Bb * Nn * Cc];
__device__ float g_V[Bb * Nn * Cc];
__device__ float g_A[Bb * Nn * Cc];

// ---------------------------------------------------------------------------
// GEMM:  C[M, 256] = A[M, 256] @ W[256, 256]^T (+ bias)
// Both A and W are K-contiguous (row-major), i.e. an NT dot-product GEMM.
// Block tile 128x64, BK=16, 256 threads, 8x4 register tile per thread.
// M = 6272 (divisible by 128), N = K = 256 -> no bounds checks needed.
// ---------------------------------------------------------------------------
__global__ __launch_bounds__(256) void gemm_nt(const float* __restrict__ A,
                                               const float* __restrict__ W,
                                               float* __restrict__ Cmat,
                                               const float* __restrict__ bias) {
    const int Kc = 256;
    const int Nc = 256;
    __shared__ float As[16][128];  // As[k][m]
    __shared__ float Ws[16][64];   // Ws[k][n]

    int tid = threadIdx.x;
    int bm  = blockIdx.x * 128;
    int bn  = blockIdx.y * 64;
    int tx  = tid & 15;   // N direction: 16 * 4 = 64
    int ty  = tid >> 4;   // M direction: 16 * 8 = 128

    float acc[8][4] = {};

    const float* Abase = A + (size_t)bm * Kc;
    const float* Wbase = W + (size_t)bn * Kc;

    for (int k0 = 0; k0 < Kc; k0 += 16) {
        // Load A tile: 128x16 = 512 float4, 2 per thread
#pragma unroll
        for (int l = 0; l < 2; l++) {
            int li = l * 256 + tid;
            int r  = li >> 2;
            int c4 = li & 3;
            float4 av = *(const float4*)(Abase + (size_t)r * Kc + k0 + c4 * 4);
            As[c4 * 4 + 0][r] = av.x;
            As[c4 * 4 + 1][r] = av.y;
            As[c4 * 4 + 2][r] = av.z;
            As[c4 * 4 + 3][r] = av.w;
        }
        // Load W tile: 64x16 = 256 float4, 1 per thread
        {
            int r  = tid >> 2;
            int c4 = tid & 3;
            float4 wv = *(const float4*)(Wbase + (size_t)r * Kc + k0 + c4 * 4);
            Ws[c4 * 4 + 0][r] = wv.x;
            Ws[c4 * 4 + 1][r] = wv.y;
            Ws[c4 * 4 + 2][r] = wv.z;
            Ws[c4 * 4 + 3][r] = wv.w;
        }
        __syncthreads();

#pragma unroll
        for (int kk = 0; kk < 16; kk++) {
            float a[8], w[4];
#pragma unroll
            for (int i = 0; i < 8; i++) a[i] = As[kk][ty * 8 + i];
#pragma unroll
            for (int j = 0; j < 4; j++) w[j] = Ws[kk][tx * 4 + j];
#pragma unroll
            for (int i = 0; i < 8; i++)
#pragma unroll
                for (int j = 0; j < 4; j++)
                    acc[i][j] = fmaf(a[i], w[j], acc[i][j]);
        }
        __syncthreads();
    }

    float bv[4] = {0.f, 0.f, 0.f, 0.f};
    if (bias) {
#pragma unroll
        for (int j = 0; j < 4; j++) bv[j] = bias[bn + tx * 4 + j];
    }
#pragma unroll
    for (int i = 0; i < 8; i++) {
        float4 o;
        o.x = acc[i][0] + bv[0];
        o.y = acc[i][1] + bv[1];
        o.z = acc[i][2] + bv[2];
        o.w = acc[i][3] + bv[3];
        *(float4*)(Cmat + (size_t)(bm + ty * 8 + i) * Nc + bn + tx * 4) = o;
    }
}

// ---------------------------------------------------------------------------
// Local windowed attention. One block per (b, n). 256 threads = C channels.
// Channel c = head*32 + d, so each warp == one head; warp-shuffle reduction
// produces the per-head dot product. Online softmax over <=29 neighbors.
// ---------------------------------------------------------------------------
__global__ __launch_bounds__(256) void local_attn(const float* __restrict__ Q,
                                                  const float* __restrict__ K,
                                                  const float* __restrict__ V,
                                                  float* __restrict__ O) {
    int bn = blockIdx.x;       // 0 .. B*N-1
    int b  = bn / Nn;
    int n  = bn - b * Nn;
    int yy = n / Hh;
    int xx = n - yy * Hh;
    int c  = threadIdx.x;

    const float scale = 0.17677669529663687f;  // 32^-0.5
    float q = Q[(size_t)bn * Cc + c] * scale;

    float m = -1e30f, s = 0.f, acc = 0.f;

    // 29 integer offsets with dy^2+dx^2 <= 9
    const int dy[29] = {-3,-2,-2,-2,-2,-2,-1,-1,-1,-1,-1, 0, 0, 0, 0, 0, 0, 0,
                         1, 1, 1, 1, 1, 2, 2, 2, 2, 2, 3};
    const int dx[29] = { 0,-2,-1, 0, 1, 2,-2,-1, 0, 1, 2,-3,-2,-1, 0, 1, 2, 3,
                        -2,-1, 0, 1, 2,-2,-1, 0, 1, 2, 0};

#pragma unroll
    for (int i = 0; i < 29; i++) {
        int ny = yy + dy[i];
        int nx = xx + dx[i];
        if ((unsigned)ny < (unsigned)Hh && (unsigned)nx < (unsigned)Hh) {
            size_t idx = ((size_t)b * Nn + ny * Hh + nx) * Cc + c;
            float kv = K[idx];
            float vv = V[idx];
            float p = q * kv;
            // per-head (per-warp) dot product
#pragma unroll
            for (int o = 16; o; o >>= 1)
                p += __shfl_xor_sync(0xffffffffu, p, o);
            // online softmax update
            float nm   = fmaxf(m, p);
            float e    = __expf(p - nm);
            float corr = __expf(m - nm);
            s   = s * corr + e;
            acc = acc * corr + e * vv;
            m = nm;
        }
    }
    O[(size_t)bn * Cc + c] = acc / s;
}

// ---------------------------------------------------------------------------
extern "C" void kernel_launch(void* const* d_in, const int* in_sizes, int n_in,
                              void* d_out, int out_size) {
    const float* x   = (const float*)d_in[0];
    const float* xkv = (const float*)d_in[1];
    const float* Wq  = (const float*)d_in[2];
    const float* Wk  = (const float*)d_in[3];
    const float* Wv  = (const float*)d_in[4];
    const float* Wp  = (const float*)d_in[5];
    const float* bp  = (const float*)d_in[6];
    float* out = (float*)d_out;

    float *Qp, *Kp, *Vp, *Ap;
    cudaGetSymbolAddress((void**)&Qp, g_Q);
    cudaGetSymbolAddress((void**)&Kp, g_K);
    cudaGetSymbolAddress((void**)&Vp, g_V);
    cudaGetSymbolAddress((void**)&Ap, g_A);

    dim3 ggrid(Bb * Nn / 128, Cc / 64);  // (49, 4)
    gemm_nt<<<ggrid, 256>>>(x,   Wq, Qp, nullptr);
    gemm_nt<<<ggrid, 256>>>(xkv, Wk, Kp, nullptr);
    gemm_nt<<<ggrid, 256>>>(xkv, Wv, Vp, nullptr);

    local_attn<<<Bb * Nn, 256>>>(Qp, Kp, Vp, Ap);

    gemm_nt<<<ggrid, 256>>>(Ap, Wp, out, bp);
}

// round 3
// speedup vs baseline: 1.4884x; 1.4884x over previous
#include <cuda_runtime.h>
#include <cuda_bf16.h>
#include <cstdint>

#define Bb 2
#define Nn 3136
#define Cc 256
#define Hh 56
#define Mtot (Bb * Nn)   // 6272

// ---------------- scratch (allocation-free) ----------------
__device__ float g_Q[Mtot * Cc];
__device__ float g_K[Mtot * Cc];
__device__ float g_V[Mtot * Cc];
__device__ __nv_bfloat16 g_xhi[Mtot * Cc], g_xlo[Mtot * Cc];
__device__ __nv_bfloat16 g_kvhi[Mtot * Cc], g_kvlo[Mtot * Cc];
__device__ __nv_bfloat16 g_ahi[Mtot * Cc], g_alo[Mtot * Cc];
__device__ __nv_bfloat16 g_whi[4 * Cc * Cc], g_wlo[4 * Cc * Cc];

// ---------------- portable (sm_80+) PTX helpers ----------------
__device__ __forceinline__ uint32_t smem_u32(const void* p) {
    uint32_t a;
    asm("{ .reg .u64 t; cvta.to.shared.u64 t, %1; cvt.u32.u64 %0, t; }" : "=r"(a) : "l"(p));
    return a;
}
__device__ __forceinline__ void cp_async16(uint32_t dst, const void* src) {
    asm volatile("cp.async.cg.shared.global [%0], [%1], 16;" :: "r"(dst), "l"(src) : "memory");
}
__device__ __forceinline__ void cp_commit() { asm volatile("cp.async.commit_group;" ::: "memory"); }
__device__ __forceinline__ void cp_wait1() { asm volatile("cp.async.wait_group 1;" ::: "memory"); }
__device__ __forceinline__ void cp_wait0() { asm volatile("cp.async.wait_group 0;" ::: "memory"); }
__device__ __forceinline__ void ldsm4(uint32_t* r, uint32_t addr) {
    asm volatile("ldmatrix.sync.aligned.m8n8.x4.shared.b16 {%0,%1,%2,%3}, [%4];"
                 : "=r"(r[0]), "=r"(r[1]), "=r"(r[2]), "=r"(r[3]) : "r"(addr));
}
__device__ __forceinline__ void mma16816(float* d, const uint32_t* a, const uint32_t* b) {
    asm volatile(
        "mma.sync.aligned.m16n8k16.row.col.f32.bf16.bf16.f32 "
        "{%0,%1,%2,%3}, {%4,%5,%6,%7}, {%8,%9}, {%0,%1,%2,%3};"
        : "+f"(d[0]), "+f"(d[1]), "+f"(d[2]), "+f"(d[3])
        : "r"(a[0]), "r"(a[1]), "r"(a[2]), "r"(a[3]), "r"(b[0]), "r"(b[1]));
}

// ---------------------------------------------------------------------------
// split: fp32 -> (hi, lo) bf16 pair, vectorized by 4
// ---------------------------------------------------------------------------
__global__ void split4(const float4* __restrict__ in, __nv_bfloat162* __restrict__ hi,
                       __nv_bfloat162* __restrict__ lo, int n4) {
    int i = blockIdx.x * blockDim.x + threadIdx.x;
    if (i >= n4) return;
    float4 v = in[i];
    __nv_bfloat16 h0 = __float2bfloat16(v.x), h1 = __float2bfloat16(v.y);
    __nv_bfloat16 h2 = __float2bfloat16(v.z), h3 = __float2bfloat16(v.w);
    hi[2 * i + 0] = __nv_bfloat162(h0, h1);
    hi[2 * i + 1] = __nv_bfloat162(h2, h3);
    lo[2 * i + 0] = __nv_bfloat162(__float2bfloat16(v.x - __bfloat162float(h0)),
                                   __float2bfloat16(v.y - __bfloat162float(h1)));
    lo[2 * i + 1] = __nv_bfloat162(__float2bfloat16(v.z - __bfloat162float(h2)),
                                   __float2bfloat16(v.w - __bfloat162float(h3)));
}

// ---------------------------------------------------------------------------
// HMMA GEMM:  out[M,256] = Ahi@Whi^T + Ahi@Wlo^T + Alo@Whi^T (+bias), fp32 out
// Block tile 128x128, K-chunk 32 bf16, 2-stage cp.async pipeline.
// 256 threads = 8 warps, warp tile 64x32 (warp grid 2m x 4n).
// Smem tiles [128][40] bf16 (80B row stride -> conflict-free ldmatrix).
// ---------------------------------------------------------------------------
#define SM_STAGE 40960        // 4 mats * 128 * 40 * 2
#define SM_MAT   10240        // 128 * 40 * 2

__global__ __launch_bounds__(256) void gemm_hmma(const __nv_bfloat16* __restrict__ Ahi,
                                                 const __nv_bfloat16* __restrict__ Alo,
                                                 const __nv_bfloat16* __restrict__ Whi,
                                                 const __nv_bfloat16* __restrict__ Wlo,
                                                 float* __restrict__ out,
                                                 const float* __restrict__ bias) {
    extern __shared__ char sm[];
    uint32_t smu = smem_u32(sm);
    float* bsm = (float*)(sm + 2 * SM_STAGE);

    const int tid = threadIdx.x;
    const int wid = tid >> 5, lane = tid & 31;
    const int m0 = blockIdx.x * 128, n0 = blockIdx.y * 128;
    const int wm = (wid >> 2) * 64, wn = (wid & 3) * 32;

    if (tid < 128) bsm[tid] = bias ? bias[n0 + tid] : 0.0f;

    const __nv_bfloat16* srcs[4] = {Ahi + (size_t)m0 * Cc, Alo + (size_t)m0 * Cc,
                                    Whi + (size_t)n0 * Cc, Wlo + (size_t)n0 * Cc};

    // async load of one K-chunk (32 bf16) into stage s
    auto load_chunk = [&](int s, int c) {
        int k0 = c * 32;
        uint32_t sb = smu + s * SM_STAGE;
#pragma unroll
        for (int i = 0; i < 8; i++) {
            int mat = i >> 1;
            int q = ((i & 1) << 8) + tid;   // 0..511 within matrix
            int row = q >> 2, j = q & 3;
            const __nv_bfloat16* g = srcs[mat] + (size_t)row * Cc + k0 + j * 8;
            cp_async16(sb + mat * SM_MAT + row * 80 + j * 16, g);
        }
        cp_commit();
    };

    float acc[4][4][4];
#pragma unroll
    for (int a = 0; a < 4; a++)
#pragma unroll
        for (int b = 0; b < 4; b++)
#pragma unroll
            for (int c = 0; c < 4; c++) acc[a][b][c] = 0.0f;

    load_chunk(0, 0);

    const int r = lane & 15, kh = lane >> 4;   // ldmatrix row-in-16, k-half

    for (int c = 0; c < 8; c++) {
        int cur = c & 1;
        if (c + 1 < 8) { load_chunk((c + 1) & 1, c + 1); cp_wait1(); }
        else           { cp_wait0(); }
        __syncthreads();

        uint32_t aH = smu + cur * SM_STAGE;
        uint32_t aL = aH + SM_MAT;
        uint32_t wH = aH + 2 * SM_MAT;
        uint32_t wL = aH + 3 * SM_MAT;

#pragma unroll
        for (int ks = 0; ks < 2; ks++) {
            int kcol = ks * 16 + kh * 8;
            uint32_t AH[4][4], AL[4][4], BH[4][2], BL[4][2];
#pragma unroll
            for (int mi = 0; mi < 4; mi++) {
                uint32_t off = (uint32_t)((wm + mi * 16 + r) * 40 + kcol) * 2;
                ldsm4(AH[mi], aH + off);
                ldsm4(AL[mi], aL + off);
            }
#pragma unroll
            for (int nj = 0; nj < 2; nj++) {
                uint32_t off = (uint32_t)((wn + nj * 16 + r) * 40 + kcol) * 2;
                uint32_t th[4], tl[4];
                ldsm4(th, wH + off);
                ldsm4(tl, wL + off);
                BH[nj * 2 + 0][0] = th[0]; BH[nj * 2 + 0][1] = th[2];
                BH[nj * 2 + 1][0] = th[1]; BH[nj * 2 + 1][1] = th[3];
                BL[nj * 2 + 0][0] = tl[0]; BL[nj * 2 + 0][1] = tl[2];
                BL[nj * 2 + 1][0] = tl[1]; BL[nj * 2 + 1][1] = tl[3];
            }
#pragma unroll
            for (int mi = 0; mi < 4; mi++)
#pragma unroll
                for (int ni = 0; ni < 4; ni++) {
                    mma16816(acc[mi][ni], AH[mi], BH[ni]);
                    mma16816(acc[mi][ni], AH[mi], BL[ni]);
                    mma16816(acc[mi][ni], AL[mi], BH[ni]);
                }
        }
        __syncthreads();
    }

    // epilogue: fp32 + bias, float2 stores
    const int g = lane >> 2, tg = lane & 3;
#pragma unroll
    for (int mi = 0; mi < 4; mi++)
#pragma unroll
        for (int ni = 0; ni < 4; ni++) {
            int row = m0 + wm + mi * 16 + g;
            int coll = wn + ni * 8 + tg * 2;       // within block n-tile
            int col = n0 + coll;
            float2 v0 = make_float2(acc[mi][ni][0] + bsm[coll],
                                    acc[mi][ni][1] + bsm[coll + 1]);
            float2 v1 = make_float2(acc[mi][ni][2] + bsm[coll],
                                    acc[mi][ni][3] + bsm[coll + 1]);
            *(float2*)(out + (size_t)row * Cc + col) = v0;
            *(float2*)(out + (size_t)(row + 8) * Cc + col) = v1;
        }
}

// ---------------------------------------------------------------------------
// Local windowed attention (radius 3 -> 29 neighbors). One block per (b, n).
// 256 threads = C channels; warp == head. Two-pass softmax, scores in regs.
// Writes bf16 hi/lo split directly for the output-projection GEMM.
// ---------------------------------------------------------------------------
__global__ __launch_bounds__(256) void local_attn(const float* __restrict__ Q,
                                                  const float* __restrict__ K,
                                                  const float* __restrict__ V,
                                                  __nv_bfloat16* __restrict__ Ohi,
                                                  __nv_bfloat16* __restrict__ Olo) {
    int bn = blockIdx.x;
    int b = bn / Nn;
    int n = bn - b * Nn;
    int yy = n / Hh;
    int xx = n - yy * Hh;
    int c = threadIdx.x;

    const float scale = 0.17677669529663687f;  // 32^-0.5
    float q = Q[(size_t)bn * Cc + c] * scale;

    const int dy[29] = {-3,-2,-2,-2,-2,-2,-1,-1,-1,-1,-1, 0, 0, 0, 0, 0, 0, 0,
                         1, 1, 1, 1, 1, 2, 2, 2, 2, 2, 3};
    const int dx[29] = { 0,-2,-1, 0, 1, 2,-2,-1, 0, 1, 2,-3,-2,-1, 0, 1, 2, 3,
                        -2,-1, 0, 1, 2,-2,-1, 0, 1, 2, 0};

    size_t base = (size_t)b * Nn;
    float sc[29];
    float m = -1e30f;
#pragma unroll
    for (int i = 0; i < 29; i++) {
        int ny = yy + dy[i], nx = xx + dx[i];
        bool ok = ((unsigned)ny < (unsigned)Hh) && ((unsigned)nx < (unsigned)Hh);
        size_t idx = (base + (ok ? ny * Hh + nx : n)) * Cc + c;
        float p = q * K[idx];
#pragma unroll
        for (int o = 16; o; o >>= 1) p += __shfl_xor_sync(0xffffffffu, p, o);
        sc[i] = ok ? p : -1e30f;
        m = fmaxf(m, sc[i]);
    }

    float s = 0.f, acc = 0.f;
#pragma unroll
    for (int i = 0; i < 29; i++) {
        int ny = yy + dy[i], nx = xx + dx[i];
        bool ok = ((unsigned)ny < (unsigned)Hh) && ((unsigned)nx < (unsigned)Hh);
        size_t idx = (base + (ok ? ny * Hh + nx : n)) * Cc + c;
        float e = __expf(sc[i] - m);
        s += e;
        acc = fmaf(e, V[idx], acc);
    }
    float o = acc / s;
    __nv_bfloat16 h = __float2bfloat16(o);
    Ohi[(size_t)bn * Cc + c] = h;
    Olo[(size_t)bn * Cc + c] = __float2bfloat16(o - __bfloat162float(h));
}

// ---------------------------------------------------------------------------
extern "C" void kernel_launch(void* const* d_in, const int* in_sizes, int n_in,
                              void* d_out, int out_size) {
    const float* x   = (const float*)d_in[0];
    const float* xkv = (const float*)d_in[1];
    const float* Wq  = (const float*)d_in[2];
    const float* Wk  = (const float*)d_in[3];
    const float* Wv  = (const float*)d_in[4];
    const float* Wp  = (const float*)d_in[5];
    const float* bp  = (const float*)d_in[6];
    float* out = (float*)d_out;

    float *Qp, *Kp, *Vp;
    __nv_bfloat16 *xhi, *xlo, *kvhi, *kvlo, *ahi, *alo, *whi, *wlo;
    cudaGetSymbolAddress((void**)&Qp, g_Q);
    cudaGetSymbolAddress((void**)&Kp, g_K);
    cudaGetSymbolAddress((void**)&Vp, g_V);
    cudaGetSymbolAddress((void**)&xhi, g_xhi);
    cudaGetSymbolAddress((void**)&xlo, g_xlo);
    cudaGetSymbolAddress((void**)&kvhi, g_kvhi);
    cudaGetSymbolAddress((void**)&kvlo, g_kvlo);
    cudaGetSymbolAddress((void**)&ahi, g_ahi);
    cudaGetSymbolAddress((void**)&alo, g_alo);
    cudaGetSymbolAddress((void**)&whi, g_whi);
    cudaGetSymbolAddress((void**)&wlo, g_wlo);

    const int SMEM_BYTES = 2 * SM_STAGE + 512;   // 82432
    cudaFuncSetAttribute(gemm_hmma, cudaFuncAttributeMaxDynamicSharedMemorySize, SMEM_BYTES);

    const int NBIG4 = Mtot * Cc / 4;
    const int NW4 = Cc * Cc / 4;
    split4<<<(NBIG4 + 255) / 256, 256>>>((const float4*)x, (__nv_bfloat162*)xhi, (__nv_bfloat162*)xlo, NBIG4);
    split4<<<(NBIG4 + 255) / 256, 256>>>((const float4*)xkv, (__nv_bfloat162*)kvhi, (__nv_bfloat162*)kvlo, NBIG4);
    split4<<<(NW4 + 255) / 256, 256>>>((const float4*)Wq, (__nv_bfloat162*)(whi), (__nv_bfloat162*)(wlo), NW4);
    split4<<<(NW4 + 255) / 256, 256>>>((const float4*)Wk, (__nv_bfloat162*)(whi + 65536), (__nv_bfloat162*)(wlo + 65536), NW4);
    split4<<<(NW4 + 255) / 256, 256>>>((const float4*)Wv, (__nv_bfloat162*)(whi + 131072), (__nv_bfloat162*)(wlo + 131072), NW4);
    split4<<<(NW4 + 255) / 256, 256>>>((const float4*)Wp, (__nv_bfloat162*)(whi + 196608), (__nv_bfloat162*)(wlo + 196608), NW4);

    dim3 ggrid(Mtot / 128, Cc / 128);  // (49, 2)
    gemm_hmma<<<ggrid, 256, SMEM_BYTES>>>(xhi, xlo, whi, wlo, Qp, nullptr);
    gemm_hmma<<<ggrid, 256, SMEM_BYTES>>>(kvhi, kvlo, whi + 65536, wlo + 65536, Kp, nullptr);
    gemm_hmma<<<ggrid, 256, SMEM_BYTES>>>(kvhi, kvlo, whi + 131072, wlo + 131072, Vp, nullptr);

    local_attn<<<Mtot, 256>>>(Qp, Kp, Vp, ahi, alo);

    gemm_hmma<<<ggrid, 256, SMEM_BYTES>>>(ahi, alo, whi + 196608, wlo + 196608, out, bp);
}

// round 4
// speedup vs baseline: 1.6856x; 1.1325x over previous
#include <cuda_runtime.h>
#include <cuda_bf16.h>
#include <cstdint>

#define Bb 2
#define Nn 3136
#define Cc 256
#define Hh 56
#define Mtot (Bb * Nn)   // 6272

// ---------------- scratch (allocation-free) ----------------
__device__ float g_Q[Mtot * Cc];
__device__ float g_K[Mtot * Cc];
__device__ float g_V[Mtot * Cc];
__device__ __nv_bfloat16 g_xhi[Mtot * Cc], g_xlo[Mtot * Cc];
__device__ __nv_bfloat16 g_kvhi[Mtot * Cc], g_kvlo[Mtot * Cc];
__device__ __nv_bfloat16 g_ahi[Mtot * Cc], g_alo[Mtot * Cc];
__device__ __nv_bfloat16 g_whi[4 * Cc * Cc], g_wlo[4 * Cc * Cc];

// ---------------- portable (sm_80+) PTX helpers ----------------
__device__ __forceinline__ uint32_t smem_u32(const void* p) {
    uint32_t a;
    asm("{ .reg .u64 t; cvta.to.shared.u64 t, %1; cvt.u32.u64 %0, t; }" : "=r"(a) : "l"(p));
    return a;
}
__device__ __forceinline__ void cp_async16(uint32_t dst, const void* src) {
    asm volatile("cp.async.cg.shared.global [%0], [%1], 16;" :: "r"(dst), "l"(src) : "memory");
}
__device__ __forceinline__ void cp_commit() { asm volatile("cp.async.commit_group;" ::: "memory"); }
__device__ __forceinline__ void cp_wait1() { asm volatile("cp.async.wait_group 1;" ::: "memory"); }
__device__ __forceinline__ void cp_wait0() { asm volatile("cp.async.wait_group 0;" ::: "memory"); }
__device__ __forceinline__ void ldsm4(uint32_t* r, uint32_t addr) {
    asm volatile("ldmatrix.sync.aligned.m8n8.x4.shared.b16 {%0,%1,%2,%3}, [%4];"
                 : "=r"(r[0]), "=r"(r[1]), "=r"(r[2]), "=r"(r[3]) : "r"(addr));
}
__device__ __forceinline__ void mma16816(float* d, const uint32_t* a, const uint32_t* b) {
    asm volatile(
        "mma.sync.aligned.m16n8k16.row.col.f32.bf16.bf16.f32 "
        "{%0,%1,%2,%3}, {%4,%5,%6,%7}, {%8,%9}, {%0,%1,%2,%3};"
        : "+f"(d[0]), "+f"(d[1]), "+f"(d[2]), "+f"(d[3])
        : "r"(a[0]), "r"(a[1]), "r"(a[2]), "r"(a[3]), "r"(b[0]), "r"(b[1]));
}

// ---------------------------------------------------------------------------
// Fused split: all 6 fp32 tensors -> (hi, lo) bf16 pairs, one launch.
// Block ranges: [0,1568) x -> xhi/xlo; [1568,3136) xkv -> kvhi/kvlo;
// [3136,3392) weights (64 blocks each) -> whi/wlo at w*32768 bf162 offset.
// ---------------------------------------------------------------------------
__global__ __launch_bounds__(256) void split_all(
    const float4* __restrict__ x, const float4* __restrict__ xkv,
    const float4* __restrict__ wq, const float4* __restrict__ wk,
    const float4* __restrict__ wv, const float4* __restrict__ wp,
    __nv_bfloat162* __restrict__ xhi, __nv_bfloat162* __restrict__ xlo,
    __nv_bfloat162* __restrict__ kvhi, __nv_bfloat162* __restrict__ kvlo,
    __nv_bfloat162* __restrict__ whi, __nv_bfloat162* __restrict__ wlo) {
    int blk = blockIdx.x;
    const float4* src;
    __nv_bfloat162 *ho, *lo_;
    int idx;
    if (blk < 1568) {
        src = x; ho = xhi; lo_ = xlo; idx = blk;
    } else if (blk < 3136) {
        src = xkv; ho = kvhi; lo_ = kvlo; idx = blk - 1568;
    } else {
        int w = (blk - 3136) >> 6;
        idx = (blk - 3136) & 63;
        src = (w == 0) ? wq : (w == 1) ? wk : (w == 2) ? wv : wp;
        ho = whi + w * 32768;
        lo_ = wlo + w * 32768;
    }
    int i = idx * 256 + threadIdx.x;
    float4 v = src[i];
    __nv_bfloat16 h0 = __float2bfloat16(v.x), h1 = __float2bfloat16(v.y);
    __nv_bfloat16 h2 = __float2bfloat16(v.z), h3 = __float2bfloat16(v.w);
    ho[2 * i + 0] = __nv_bfloat162(h0, h1);
    ho[2 * i + 1] = __nv_bfloat162(h2, h3);
    lo_[2 * i + 0] = __nv_bfloat162(__float2bfloat16(v.x - __bfloat162float(h0)),
                                    __float2bfloat16(v.y - __bfloat162float(h1)));
    lo_[2 * i + 1] = __nv_bfloat162(__float2bfloat16(v.z - __bfloat162float(h2)),
                                    __float2bfloat16(v.w - __bfloat162float(h3)));
}

// ---------------------------------------------------------------------------
// HMMA GEMM:  out[M,256] = Ahi@Whi^T + Ahi@Wlo^T + Alo@Whi^T (+bias), fp32 out
// Block tile 64x128 (grid 98x2 = 196 CTAs), K-chunk 32, 2-stage cp.async.
// 256 threads = 8 warps, warp grid 2m x 4n, warp tile 32x32.
// Smem rows padded to 40 bf16 (80B) -> conflict-free ldmatrix.
// ---------------------------------------------------------------------------
#define SM_A     5120          // 64 * 40 * 2
#define SM_W     10240         // 128 * 40 * 2
#define SM_STAGE 30720         // 2*SM_A + 2*SM_W

__global__ __launch_bounds__(256) void gemm_hmma(const __nv_bfloat16* __restrict__ Ahi,
                                                 const __nv_bfloat16* __restrict__ Alo,
                                                 const __nv_bfloat16* __restrict__ Whi,
                                                 const __nv_bfloat16* __restrict__ Wlo,
                                                 float* __restrict__ out,
                                                 const float* __restrict__ bias) {
    extern __shared__ char sm[];
    uint32_t smu = smem_u32(sm);
    float* bsm = (float*)(sm + 2 * SM_STAGE);

    const int tid = threadIdx.x;
    const int wid = tid >> 5, lane = tid & 31;
    const int m0 = blockIdx.x * 64, n0 = blockIdx.y * 128;
    const int wm = (wid >> 2) * 32, wn = (wid & 3) * 32;

    if (tid < 128) bsm[tid] = bias ? bias[n0 + tid] : 0.0f;

    const __nv_bfloat16* aH = Ahi + (size_t)m0 * Cc;
    const __nv_bfloat16* aL = Alo + (size_t)m0 * Cc;
    const __nv_bfloat16* wH = Whi + (size_t)n0 * Cc;
    const __nv_bfloat16* wL = Wlo + (size_t)n0 * Cc;

    auto load_chunk = [&](int s, int c) {
        int k0 = c * 32;
        uint32_t sb = smu + s * SM_STAGE;
        {   // A mats: 64 rows x 4 vec16 = 256 ops each, 1/thread
            int row = tid >> 2, j = tid & 3;
            const __nv_bfloat16* gh = aH + (size_t)row * Cc + k0 + j * 8;
            const __nv_bfloat16* gl = aL + (size_t)row * Cc + k0 + j * 8;
            cp_async16(sb + row * 80 + j * 16, gh);
            cp_async16(sb + SM_A + row * 80 + j * 16, gl);
        }
#pragma unroll
        for (int h = 0; h < 2; h++) {  // W mats: 128 rows x 4 = 512 ops each, 2/thread
            int q = h * 256 + tid;
            int row = q >> 2, j = q & 3;
            const __nv_bfloat16* gh = wH + (size_t)row * Cc + k0 + j * 8;
            const __nv_bfloat16* gl = wL + (size_t)row * Cc + k0 + j * 8;
            cp_async16(sb + 2 * SM_A + row * 80 + j * 16, gh);
            cp_async16(sb + 2 * SM_A + SM_W + row * 80 + j * 16, gl);
        }
        cp_commit();
    };

    float acc[2][4][4];
#pragma unroll
    for (int a = 0; a < 2; a++)
#pragma unroll
        for (int b = 0; b < 4; b++)
#pragma unroll
            for (int c = 0; c < 4; c++) acc[a][b][c] = 0.0f;

    load_chunk(0, 0);

    const int r = lane & 15, kh = lane >> 4;

    for (int c = 0; c < 8; c++) {
        int cur = c & 1;
        if (c + 1 < 8) { load_chunk((c + 1) & 1, c + 1); cp_wait1(); }
        else           { cp_wait0(); }
        __syncthreads();

        uint32_t sAH = smu + cur * SM_STAGE;
        uint32_t sAL = sAH + SM_A;
        uint32_t sWH = sAH + 2 * SM_A;
        uint32_t sWL = sWH + SM_W;

#pragma unroll
        for (int ks = 0; ks < 2; ks++) {
            int kcol = ks * 16 + kh * 8;
            uint32_t AH[2][4], AL[2][4], BH[4][2], BL[4][2];
#pragma unroll
            for (int mi = 0; mi < 2; mi++) {
                uint32_t off = (uint32_t)((wm + mi * 16 + r) * 40 + kcol) * 2;
                ldsm4(AH[mi], sAH + off);
                ldsm4(AL[mi], sAL + off);
            }
#pragma unroll
            for (int nj = 0; nj < 2; nj++) {
                uint32_t off = (uint32_t)((wn + nj * 16 + r) * 40 + kcol) * 2;
                uint32_t th[4], tl[4];
                ldsm4(th, sWH + off);
                ldsm4(tl, sWL + off);
                BH[nj * 2 + 0][0] = th[0]; BH[nj * 2 + 0][1] = th[2];
                BH[nj * 2 + 1][0] = th[1]; BH[nj * 2 + 1][1] = th[3];
                BL[nj * 2 + 0][0] = tl[0]; BL[nj * 2 + 0][1] = tl[2];
                BL[nj * 2 + 1][0] = tl[1]; BL[nj * 2 + 1][1] = tl[3];
            }
#pragma unroll
            for (int mi = 0; mi < 2; mi++)
#pragma unroll
                for (int ni = 0; ni < 4; ni++) {
                    mma16816(acc[mi][ni], AH[mi], BH[ni]);
                    mma16816(acc[mi][ni], AH[mi], BL[ni]);
                    mma16816(acc[mi][ni], AL[mi], BH[ni]);
                }
        }
        __syncthreads();
    }

    const int g = lane >> 2, tg = lane & 3;
#pragma unroll
    for (int mi = 0; mi < 2; mi++)
#pragma unroll
        for (int ni = 0; ni < 4; ni++) {
            int row = m0 + wm + mi * 16 + g;
            int coll = wn + ni * 8 + tg * 2;
            int col = n0 + coll;
            float2 v0 = make_float2(acc[mi][ni][0] + bsm[coll],
                                    acc[mi][ni][1] + bsm[coll + 1]);
            float2 v1 = make_float2(acc[mi][ni][2] + bsm[coll],
                                    acc[mi][ni][3] + bsm[coll + 1]);
            *(float2*)(out + (size_t)row * Cc + col) = v0;
            *(float2*)(out + (size_t)(row + 8) * Cc + col) = v1;
        }
}

// ---------------------------------------------------------------------------
// Local windowed attention (radius 3 -> 29 neighbors).
// 4 queries per block; 64 threads per query; each thread owns 4 channels
// (float4). Head = group of 8 lanes -> 3-shuffle dot reduction.
// Two-pass softmax; neighbor offsets cached in regs. bf16 hi/lo epilogue.
// ---------------------------------------------------------------------------
struct alignas(8) bf16x4 { __nv_bfloat162 a, b; };

__global__ __launch_bounds__(256) void local_attn(const float* __restrict__ Q,
                                                  const float* __restrict__ K,
                                                  const float* __restrict__ V,
                                                  __nv_bfloat16* __restrict__ Ohi,
                                                  __nv_bfloat16* __restrict__ Olo) {
    int slot = threadIdx.x >> 6;
    int t = threadIdx.x & 63;
    int bn = blockIdx.x * 4 + slot;
    int b = bn / Nn;
    int n = bn - b * Nn;
    int yy = n / Hh;
    int xx = n - yy * Hh;

    const float scale = 0.17677669529663687f;  // 32^-0.5
    size_t qoff = (size_t)bn * Cc + t * 4;
    float4 q4 = *(const float4*)(Q + qoff);
    q4.x *= scale; q4.y *= scale; q4.z *= scale; q4.w *= scale;

    const int dy[29] = {-3,-2,-2,-2,-2,-2,-1,-1,-1,-1,-1, 0, 0, 0, 0, 0, 0, 0,
                         1, 1, 1, 1, 1, 2, 2, 2, 2, 2, 3};
    const int dx[29] = { 0,-2,-1, 0, 1, 2,-2,-1, 0, 1, 2,-3,-2,-1, 0, 1, 2, 3,
                        -2,-1, 0, 1, 2,-2,-1, 0, 1, 2, 0};

    size_t base = (size_t)b * Nn;
    int off[29];
    float sc[29];
    float m = -1e30f;
#pragma unroll
    for (int i = 0; i < 29; i++) {
        int ny = yy + dy[i], nx = xx + dx[i];
        bool ok = ((unsigned)ny < (unsigned)Hh) && ((unsigned)nx < (unsigned)Hh);
        int nn = ok ? ny * Hh + nx : n;
        off[i] = nn;
        const float4 k4 = *(const float4*)(K + (base + nn) * Cc + t * 4);
        float p = q4.x * k4.x + q4.y * k4.y + q4.z * k4.z + q4.w * k4.w;
        p += __shfl_xor_sync(0xffffffffu, p, 1);
        p += __shfl_xor_sync(0xffffffffu, p, 2);
        p += __shfl_xor_sync(0xffffffffu, p, 4);
        sc[i] = ok ? p : -1e30f;
        m = fmaxf(m, sc[i]);
    }

    float s = 0.f;
    float4 acc = make_float4(0.f, 0.f, 0.f, 0.f);
#pragma unroll
    for (int i = 0; i < 29; i++) {
        float e = __expf(sc[i] - m);
        s += e;
        const float4 v4 = *(const float4*)(V + (base + off[i]) * Cc + t * 4);
        acc.x = fmaf(e, v4.x, acc.x);
        acc.y = fmaf(e, v4.y, acc.y);
        acc.z = fmaf(e, v4.z, acc.z);
        acc.w = fmaf(e, v4.w, acc.w);
    }
    float inv = __fdividef(1.0f, s);
    float4 o = make_float4(acc.x * inv, acc.y * inv, acc.z * inv, acc.w * inv);

    __nv_bfloat16 h0 = __float2bfloat16(o.x), h1 = __float2bfloat16(o.y);
    __nv_bfloat16 h2 = __float2bfloat16(o.z), h3 = __float2bfloat16(o.w);
    bf16x4 hv, lv;
    hv.a = __nv_bfloat162(h0, h1);
    hv.b = __nv_bfloat162(h2, h3);
    lv.a = __nv_bfloat162(__float2bfloat16(o.x - __bfloat162float(h0)),
                          __float2bfloat16(o.y - __bfloat162float(h1)));
    lv.b = __nv_bfloat162(__float2bfloat16(o.z - __bfloat162float(h2)),
                          __float2bfloat16(o.w - __bfloat162float(h3)));
    *(bf16x4*)(Ohi + qoff) = hv;
    *(bf16x4*)(Olo + qoff) = lv;
}

// ---------------------------------------------------------------------------
extern "C" void kernel_launch(void* const* d_in, const int* in_sizes, int n_in,
                              void* d_out, int out_size) {
    const float* x   = (const float*)d_in[0];
    const float* xkv = (const float*)d_in[1];
    const float* Wq  = (const float*)d_in[2];
    const float* Wk  = (const float*)d_in[3];
    const float* Wv  = (const float*)d_in[4];
    const float* Wp  = (const float*)d_in[5];
    const float* bp  = (const float*)d_in[6];
    float* out = (float*)d_out;

    float *Qp, *Kp, *Vp;
    __nv_bfloat16 *xhi, *xlo, *kvhi, *kvlo, *ahi, *alo, *whi, *wlo;
    cudaGetSymbolAddress((void**)&Qp, g_Q);
    cudaGetSymbolAddress((void**)&Kp, g_K);
    cudaGetSymbolAddress((void**)&Vp, g_V);
    cudaGetSymbolAddress((void**)&xhi, g_xhi);
    cudaGetSymbolAddress((void**)&xlo, g_xlo);
    cudaGetSymbolAddress((void**)&kvhi, g_kvhi);
    cudaGetSymbolAddress((void**)&kvlo, g_kvlo);
    cudaGetSymbolAddress((void**)&ahi, g_ahi);
    cudaGetSymbolAddress((void**)&alo, g_alo);
    cudaGetSymbolAddress((void**)&whi, g_whi);
    cudaGetSymbolAddress((void**)&wlo, g_wlo);

    const int SMEM_BYTES = 2 * SM_STAGE + 512;   // 61952
    cudaFuncSetAttribute(gemm_hmma, cudaFuncAttributeMaxDynamicSharedMemorySize, SMEM_BYTES);

    split_all<<<3392, 256>>>((const float4*)x, (const float4*)xkv,
                             (const float4*)Wq, (const float4*)Wk,
                             (const float4*)Wv, (const float4*)Wp,
                             (__nv_bfloat162*)xhi, (__nv_bfloat162*)xlo,
                             (__nv_bfloat162*)kvhi, (__nv_bfloat162*)kvlo,
                             (__nv_bfloat162*)whi, (__nv_bfloat162*)wlo);

    dim3 ggrid(Mtot / 64, Cc / 128);  // (98, 2)
    gemm_hmma<<<ggrid, 256, SMEM_BYTES>>>(xhi, xlo, whi, wlo, Qp, nullptr);
    gemm_hmma<<<ggrid, 256, SMEM_BYTES>>>(kvhi, kvlo, whi + 65536, wlo + 65536, Kp, nullptr);
    gemm_hmma<<<ggrid, 256, SMEM_BYTES>>>(kvhi, kvlo, whi + 131072, wlo + 131072, Vp, nullptr);

    local_attn<<<Mtot / 4, 256>>>(Qp, Kp, Vp, ahi, alo);

    gemm_hmma<<<ggrid, 256, SMEM_BYTES>>>(ahi, alo, whi + 196608, wlo + 196608, out, bp);
}

// round 5
// speedup vs baseline: 2.0446x; 1.2130x over previous
#include <cuda_runtime.h>
#include <cuda_bf16.h>
#include <cstdint>

#define Bb 2
#define Nn 3136
#define Cc 256
#define Hh 56
#define Mtot (Bb * Nn)   // 6272

// ---------------- scratch (allocation-free) ----------------
__device__ float g_Q[Mtot * Cc];
__device__ float g_K[Mtot * Cc];
__device__ float g_V[Mtot * Cc];
__device__ __nv_bfloat16 g_xhi[Mtot * Cc], g_xlo[Mtot * Cc];
__device__ __nv_bfloat16 g_kvhi[Mtot * Cc], g_kvlo[Mtot * Cc];
__device__ __nv_bfloat16 g_ahi[Mtot * Cc], g_alo[Mtot * Cc];
__device__ __nv_bfloat16 g_whi[4 * Cc * Cc], g_wlo[4 * Cc * Cc];

// ---------------- portable (sm_80+) PTX helpers ----------------
__device__ __forceinline__ uint32_t smem_u32(const void* p) {
    uint32_t a;
    asm("{ .reg .u64 t; cvta.to.shared.u64 t, %1; cvt.u32.u64 %0, t; }" : "=r"(a) : "l"(p));
    return a;
}
__device__ __forceinline__ void cp_async16(uint32_t dst, const void* src) {
    asm volatile("cp.async.cg.shared.global [%0], [%1], 16;" :: "r"(dst), "l"(src) : "memory");
}
__device__ __forceinline__ void cp_commit() { asm volatile("cp.async.commit_group;" ::: "memory"); }
__device__ __forceinline__ void cp_wait1() { asm volatile("cp.async.wait_group 1;" ::: "memory"); }
__device__ __forceinline__ void cp_wait0() { asm volatile("cp.async.wait_group 0;" ::: "memory"); }
__device__ __forceinline__ void ldsm4(uint32_t* r, uint32_t addr) {
    asm volatile("ldmatrix.sync.aligned.m8n8.x4.shared.b16 {%0,%1,%2,%3}, [%4];"
                 : "=r"(r[0]), "=r"(r[1]), "=r"(r[2]), "=r"(r[3]) : "r"(addr));
}
__device__ __forceinline__ void mma16816(float* d, const uint32_t* a, const uint32_t* b) {
    asm volatile(
        "mma.sync.aligned.m16n8k16.row.col.f32.bf16.bf16.f32 "
        "{%0,%1,%2,%3}, {%4,%5,%6,%7}, {%8,%9}, {%0,%1,%2,%3};"
        : "+f"(d[0]), "+f"(d[1]), "+f"(d[2]), "+f"(d[3])
        : "r"(a[0]), "r"(a[1]), "r"(a[2]), "r"(a[3]), "r"(b[0]), "r"(b[1]));
}

// ---------------------------------------------------------------------------
// Fused split: all 6 fp32 tensors -> (hi, lo) bf16 pairs, one launch.
// ---------------------------------------------------------------------------
__global__ __launch_bounds__(256) void split_all(
    const float4* __restrict__ x, const float4* __restrict__ xkv,
    const float4* __restrict__ wq, const float4* __restrict__ wk,
    const float4* __restrict__ wv, const float4* __restrict__ wp,
    __nv_bfloat162* __restrict__ xhi, __nv_bfloat162* __restrict__ xlo,
    __nv_bfloat162* __restrict__ kvhi, __nv_bfloat162* __restrict__ kvlo,
    __nv_bfloat162* __restrict__ whi, __nv_bfloat162* __restrict__ wlo) {
    int blk = blockIdx.x;
    const float4* src;
    __nv_bfloat162 *ho, *lo_;
    int idx;
    if (blk < 1568) {
        src = x; ho = xhi; lo_ = xlo; idx = blk;
    } else if (blk < 3136) {
        src = xkv; ho = kvhi; lo_ = kvlo; idx = blk - 1568;
    } else {
        int w = (blk - 3136) >> 6;
        idx = (blk - 3136) & 63;
        src = (w == 0) ? wq : (w == 1) ? wk : (w == 2) ? wv : wp;
        ho = whi + w * 32768;
        lo_ = wlo + w * 32768;
    }
    int i = idx * 256 + threadIdx.x;
    float4 v = src[i];
    __nv_bfloat16 h0 = __float2bfloat16(v.x), h1 = __float2bfloat16(v.y);
    __nv_bfloat16 h2 = __float2bfloat16(v.z), h3 = __float2bfloat16(v.w);
    ho[2 * i + 0] = __nv_bfloat162(h0, h1);
    ho[2 * i + 1] = __nv_bfloat162(h2, h3);
    lo_[2 * i + 0] = __nv_bfloat162(__float2bfloat16(v.x - __bfloat162float(h0)),
                                    __float2bfloat16(v.y - __bfloat162float(h1)));
    lo_[2 * i + 1] = __nv_bfloat162(__float2bfloat16(v.z - __bfloat162float(h2)),
                                    __float2bfloat16(v.w - __bfloat162float(h3)));
}

// ---------------------------------------------------------------------------
// HMMA GEMM body: out[64x128 tile] = Ahi@Whi^T + Ahi@Wlo^T + Alo@Whi^T (+bias)
// 3-stage depth-2 cp.async pipeline, ONE __syncthreads per K-chunk.
// 256 threads = 8 warps, warp grid 2m x 4n, warp tile 32x32.
// Smem rows padded to 40 bf16 (80B) -> conflict-free ldmatrix.
// ---------------------------------------------------------------------------
#define SM_A     5120          // 64 * 40 * 2
#define SM_W     10240         // 128 * 40 * 2
#define SM_STAGE 30720         // 2*SM_A + 2*SM_W
#define N_STAGE  3
#define SMEM_BYTES (N_STAGE * SM_STAGE + 512)

__device__ __forceinline__ void gemm_body(const __nv_bfloat16* __restrict__ Ahi,
                                          const __nv_bfloat16* __restrict__ Alo,
                                          const __nv_bfloat16* __restrict__ Whi,
                                          const __nv_bfloat16* __restrict__ Wlo,
                                          float* __restrict__ out,
                                          const float* __restrict__ bias,
                                          int m0, int n0, char* sm) {
    uint32_t smu = smem_u32(sm);
    float* bsm = (float*)(sm + N_STAGE * SM_STAGE);

    const int tid = threadIdx.x;
    const int wid = tid >> 5, lane = tid & 31;
    const int wm = (wid >> 2) * 32, wn = (wid & 3) * 32;

    if (tid < 128) bsm[tid] = bias ? bias[n0 + tid] : 0.0f;

    const __nv_bfloat16* aH = Ahi + (size_t)m0 * Cc;
    const __nv_bfloat16* aL = Alo + (size_t)m0 * Cc;
    const __nv_bfloat16* wH = Whi + (size_t)n0 * Cc;
    const __nv_bfloat16* wL = Wlo + (size_t)n0 * Cc;

    auto load_chunk = [&](int s, int c) {
        int k0 = c * 32;
        uint32_t sb = smu + s * SM_STAGE;
        {   // A mats: 64 rows x 4 vec16
            int row = tid >> 2, j = tid & 3;
            cp_async16(sb + row * 80 + j * 16, aH + (size_t)row * Cc + k0 + j * 8);
            cp_async16(sb + SM_A + row * 80 + j * 16, aL + (size_t)row * Cc + k0 + j * 8);
        }
#pragma unroll
        for (int h = 0; h < 2; h++) {  // W mats: 128 rows x 4
            int q = h * 256 + tid;
            int row = q >> 2, j = q & 3;
            cp_async16(sb + 2 * SM_A + row * 80 + j * 16, wH + (size_t)row * Cc + k0 + j * 8);
            cp_async16(sb + 2 * SM_A + SM_W + row * 80 + j * 16, wL + (size_t)row * Cc + k0 + j * 8);
        }
        cp_commit();
    };

    float acc[2][4][4];
#pragma unroll
    for (int a = 0; a < 2; a++)
#pragma unroll
        for (int b = 0; b < 4; b++)
#pragma unroll
            for (int c = 0; c < 4; c++) acc[a][b][c] = 0.0f;

    load_chunk(0, 0);
    load_chunk(1, 1);

    const int r = lane & 15, kh = lane >> 4;

    for (int c = 0; c < 8; c++) {
        if (c < 7) cp_wait1();   // group c complete (groups finish in order)
        else       cp_wait0();
        __syncthreads();
        if (c + 2 < 8) load_chunk((c + 2) % N_STAGE, c + 2);

        int cur = c % N_STAGE;
        uint32_t sAH = smu + cur * SM_STAGE;
        uint32_t sAL = sAH + SM_A;
        uint32_t sWH = sAH + 2 * SM_A;
        uint32_t sWL = sWH + SM_W;

#pragma unroll
        for (int ks = 0; ks < 2; ks++) {
            int kcol = ks * 16 + kh * 8;
            uint32_t AH[2][4], AL[2][4], BH[4][2], BL[4][2];
#pragma unroll
            for (int mi = 0; mi < 2; mi++) {
                uint32_t off = (uint32_t)((wm + mi * 16 + r) * 40 + kcol) * 2;
                ldsm4(AH[mi], sAH + off);
                ldsm4(AL[mi], sAL + off);
            }
#pragma unroll
            for (int nj = 0; nj < 2; nj++) {
                uint32_t off = (uint32_t)((wn + nj * 16 + r) * 40 + kcol) * 2;
                uint32_t th[4], tl[4];
                ldsm4(th, sWH + off);
                ldsm4(tl, sWL + off);
                BH[nj * 2 + 0][0] = th[0]; BH[nj * 2 + 0][1] = th[2];
                BH[nj * 2 + 1][0] = th[1]; BH[nj * 2 + 1][1] = th[3];
                BL[nj * 2 + 0][0] = tl[0]; BL[nj * 2 + 0][1] = tl[2];
                BL[nj * 2 + 1][0] = tl[1]; BL[nj * 2 + 1][1] = tl[3];
            }
#pragma unroll
            for (int mi = 0; mi < 2; mi++)
#pragma unroll
                for (int ni = 0; ni < 4; ni++) {
                    mma16816(acc[mi][ni], AH[mi], BH[ni]);
                    mma16816(acc[mi][ni], AH[mi], BL[ni]);
                    mma16816(acc[mi][ni], AL[mi], BH[ni]);
                }
        }
    }

    const int g = lane >> 2, tg = lane & 3;
#pragma unroll
    for (int mi = 0; mi < 2; mi++)
#pragma unroll
        for (int ni = 0; ni < 4; ni++) {
            int row = m0 + wm + mi * 16 + g;
            int coll = wn + ni * 8 + tg * 2;
            int col = n0 + coll;
            float2 v0 = make_float2(acc[mi][ni][0] + bsm[coll],
                                    acc[mi][ni][1] + bsm[coll + 1]);
            float2 v1 = make_float2(acc[mi][ni][2] + bsm[coll],
                                    acc[mi][ni][3] + bsm[coll + 1]);
            *(float2*)(out + (size_t)row * Cc + col) = v0;
            *(float2*)(out + (size_t)(row + 8) * Cc + col) = v1;
        }
}

// Fused Q/K/V projections: grid (98, 2, 3); z selects {x@Wq, xkv@Wk, xkv@Wv}.
__global__ __launch_bounds__(256) void gemm_qkv(
    const __nv_bfloat16* __restrict__ xhi, const __nv_bfloat16* __restrict__ xlo,
    const __nv_bfloat16* __restrict__ kvhi, const __nv_bfloat16* __restrict__ kvlo,
    const __nv_bfloat16* __restrict__ whi, const __nv_bfloat16* __restrict__ wlo,
    float* __restrict__ Q, float* __restrict__ K, float* __restrict__ V) {
    extern __shared__ char sm[];
    int z = blockIdx.z;
    const __nv_bfloat16* Ahi = (z == 0) ? xhi : kvhi;
    const __nv_bfloat16* Alo = (z == 0) ? xlo : kvlo;
    const __nv_bfloat16* Wh = whi + (size_t)z * 65536;
    const __nv_bfloat16* Wl = wlo + (size_t)z * 65536;
    float* out = (z == 0) ? Q : (z == 1) ? K : V;
    gemm_body(Ahi, Alo, Wh, Wl, out, nullptr, blockIdx.x * 64, blockIdx.y * 128, sm);
}

// Output projection (with bias).
__global__ __launch_bounds__(256) void gemm_out(
    const __nv_bfloat16* __restrict__ Ahi, const __nv_bfloat16* __restrict__ Alo,
    const __nv_bfloat16* __restrict__ Whi, const __nv_bfloat16* __restrict__ Wlo,
    float* __restrict__ out, const float* __restrict__ bias) {
    extern __shared__ char sm[];
    gemm_body(Ahi, Alo, Whi, Wlo, out, bias, blockIdx.x * 64, blockIdx.y * 128, sm);
}

// ---------------------------------------------------------------------------
// Local windowed attention (radius 3 -> 29 neighbors).
// 4 queries per block; 64 threads per query; each thread owns 4 channels.
// Head = group of 8 lanes -> 3-shuffle dot reduction. Two-pass softmax.
// ---------------------------------------------------------------------------
struct alignas(8) bf16x4 { __nv_bfloat162 a, b; };

__global__ __launch_bounds__(256) void local_attn(const float* __restrict__ Q,
                                                  const float* __restrict__ K,
                                                  const float* __restrict__ V,
                                                  __nv_bfloat16* __restrict__ Ohi,
                                                  __nv_bfloat16* __restrict__ Olo) {
    int slot = threadIdx.x >> 6;
    int t = threadIdx.x & 63;
    int bn = blockIdx.x * 4 + slot;
    int b = bn / Nn;
    int n = bn - b * Nn;
    int yy = n / Hh;
    int xx = n - yy * Hh;

    const float scale = 0.17677669529663687f;  // 32^-0.5
    size_t qoff = (size_t)bn * Cc + t * 4;
    float4 q4 = *(const float4*)(Q + qoff);
    q4.x *= scale; q4.y *= scale; q4.z *= scale; q4.w *= scale;

    const int dy[29] = {-3,-2,-2,-2,-2,-2,-1,-1,-1,-1,-1, 0, 0, 0, 0, 0, 0, 0,
                         1, 1, 1, 1, 1, 2, 2, 2, 2, 2, 3};
    const int dx[29] = { 0,-2,-1, 0, 1, 2,-2,-1, 0, 1, 2,-3,-2,-1, 0, 1, 2, 3,
                        -2,-1, 0, 1, 2,-2,-1, 0, 1, 2, 0};

    size_t base = (size_t)b * Nn;
    int off[29];
    float sc[29];
    float m = -1e30f;
#pragma unroll
    for (int i = 0; i < 29; i++) {
        int ny = yy + dy[i], nx = xx + dx[i];
        bool ok = ((unsigned)ny < (unsigned)Hh) && ((unsigned)nx < (unsigned)Hh);
        int nn = ok ? ny * Hh + nx : n;
        off[i] = nn;
        const float4 k4 = *(const float4*)(K + (base + nn) * Cc + t * 4);
        float p = q4.x * k4.x + q4.y * k4.y + q4.z * k4.z + q4.w * k4.w;
        p += __shfl_xor_sync(0xffffffffu, p, 1);
        p += __shfl_xor_sync(0xffffffffu, p, 2);
        p += __shfl_xor_sync(0xffffffffu, p, 4);
        sc[i] = ok ? p : -1e30f;
        m = fmaxf(m, sc[i]);
    }

    float s = 0.f;
    float4 acc = make_float4(0.f, 0.f, 0.f, 0.f);
#pragma unroll
    for (int i = 0; i < 29; i++) {
        float e = __expf(sc[i] - m);
        s += e;
        const float4 v4 = *(const float4*)(V + (base + off[i]) * Cc + t * 4);
        acc.x = fmaf(e, v4.x, acc.x);
        acc.y = fmaf(e, v4.y, acc.y);
        acc.z = fmaf(e, v4.z, acc.z);
        acc.w = fmaf(e, v4.w, acc.w);
    }
    float inv = __fdividef(1.0f, s);
    float4 o = make_float4(acc.x * inv, acc.y * inv, acc.z * inv, acc.w * inv);

    __nv_bfloat16 h0 = __float2bfloat16(o.x), h1 = __float2bfloat16(o.y);
    __nv_bfloat16 h2 = __float2bfloat16(o.z), h3 = __float2bfloat16(o.w);
    bf16x4 hv, lv;
    hv.a = __nv_bfloat162(h0, h1);
    hv.b = __nv_bfloat162(h2, h3);
    lv.a = __nv_bfloat162(__float2bfloat16(o.x - __bfloat162float(h0)),
                          __float2bfloat16(o.y - __bfloat162float(h1)));
    lv.b = __nv_bfloat162(__float2bfloat16(o.z - __bfloat162float(h2)),
                          __float2bfloat16(o.w - __bfloat162float(h3)));
    *(bf16x4*)(Ohi + qoff) = hv;
    *(bf16x4*)(Olo + qoff) = lv;
}

// ---------------------------------------------------------------------------
extern "C" void kernel_launch(void* const* d_in, const int* in_sizes, int n_in,
                              void* d_out, int out_size) {
    const float* x   = (const float*)d_in[0];
    const float* xkv = (const float*)d_in[1];
    const float* Wq  = (const float*)d_in[2];
    const float* Wk  = (const float*)d_in[3];
    const float* Wv  = (const float*)d_in[4];
    const float* Wp  = (const float*)d_in[5];
    const float* bp  = (const float*)d_in[6];
    float* out = (float*)d_out;

    float *Qp, *Kp, *Vp;
    __nv_bfloat16 *xhi, *xlo, *kvhi, *kvlo, *ahi, *alo, *whi, *wlo;
    cudaGetSymbolAddress((void**)&Qp, g_Q);
    cudaGetSymbolAddress((void**)&Kp, g_K);
    cudaGetSymbolAddress((void**)&Vp, g_V);
    cudaGetSymbolAddress((void**)&xhi, g_xhi);
    cudaGetSymbolAddress((void**)&xlo, g_xlo);
    cudaGetSymbolAddress((void**)&kvhi, g_kvhi);
    cudaGetSymbolAddress((void**)&kvlo, g_kvlo);
    cudaGetSymbolAddress((void**)&ahi, g_ahi);
    cudaGetSymbolAddress((void**)&alo, g_alo);
    cudaGetSymbolAddress((void**)&whi, g_whi);
    cudaGetSymbolAddress((void**)&wlo, g_wlo);

    cudaFuncSetAttribute(gemm_qkv, cudaFuncAttributeMaxDynamicSharedMemorySize, SMEM_BYTES);
    cudaFuncSetAttribute(gemm_out, cudaFuncAttributeMaxDynamicSharedMemorySize, SMEM_BYTES);

    split_all<<<3392, 256>>>((const float4*)x, (const float4*)xkv,
                             (const float4*)Wq, (const float4*)Wk,
                             (const float4*)Wv, (const float4*)Wp,
                             (__nv_bfloat162*)xhi, (__nv_bfloat162*)xlo,
                             (__nv_bfloat162*)kvhi, (__nv_bfloat162*)kvlo,
                             (__nv_bfloat162*)whi, (__nv_bfloat162*)wlo);

    dim3 gqkv(Mtot / 64, Cc / 128, 3);   // (98, 2, 3) = 588 CTAs
    gemm_qkv<<<gqkv, 256, SMEM_BYTES>>>(xhi, xlo, kvhi, kvlo, whi, wlo, Qp, Kp, Vp);

    local_attn<<<Mtot / 4, 256>>>(Qp, Kp, Vp, ahi, alo);

    dim3 gout(Mtot / 64, Cc / 128);      // (98, 2)
    gemm_out<<<gout, 256, SMEM_BYTES>>>(ahi, alo, whi + 196608, wlo + 196608, out, bp);
}

// round 6
// speedup vs baseline: 2.0860x; 1.0203x over previous
#include <cuda_runtime.h>
#include <cuda_bf16.h>
#include <cstdint>

#define Bb 2
#define Nn 3136
#define Cc 256
#define Hh 56
#define Mtot (Bb * Nn)   // 6272

// ---------------- scratch (allocation-free) ----------------
__device__ float g_Q[Mtot * Cc];
__device__ float g_K[Mtot * Cc];
__device__ float g_V[Mtot * Cc];
__device__ __nv_bfloat16 g_xhi[Mtot * Cc], g_xlo[Mtot * Cc];
__device__ __nv_bfloat16 g_kvhi[Mtot * Cc], g_kvlo[Mtot * Cc];
__device__ __nv_bfloat16 g_ahi[Mtot * Cc], g_alo[Mtot * Cc];
__device__ __nv_bfloat16 g_whi[4 * Cc * Cc], g_wlo[4 * Cc * Cc];

// ---------------- portable (sm_80+) PTX helpers ----------------
__device__ __forceinline__ uint32_t smem_u32(const void* p) {
    uint32_t a;
    asm("{ .reg .u64 t; cvta.to.shared.u64 t, %1; cvt.u32.u64 %0, t; }" : "=r"(a) : "l"(p));
    return a;
}
__device__ __forceinline__ void cp_async16(uint32_t dst, const void* src) {
    asm volatile("cp.async.cg.shared.global [%0], [%1], 16;" :: "r"(dst), "l"(src) : "memory");
}
__device__ __forceinline__ void cp_commit() { asm volatile("cp.async.commit_group;" ::: "memory"); }
__device__ __forceinline__ void cp_wait1() { asm volatile("cp.async.wait_group 1;" ::: "memory"); }
__device__ __forceinline__ void cp_wait0() { asm volatile("cp.async.wait_group 0;" ::: "memory"); }
__device__ __forceinline__ void ldsm4(uint32_t* r, uint32_t addr) {
    asm volatile("ldmatrix.sync.aligned.m8n8.x4.shared.b16 {%0,%1,%2,%3}, [%4];"
                 : "=r"(r[0]), "=r"(r[1]), "=r"(r[2]), "=r"(r[3]) : "r"(addr));
}
__device__ __forceinline__ void mma16816(float* d, const uint32_t* a, const uint32_t* b) {
    asm volatile(
        "mma.sync.aligned.m16n8k16.row.col.f32.bf16.bf16.f32 "
        "{%0,%1,%2,%3}, {%4,%5,%6,%7}, {%8,%9}, {%0,%1,%2,%3};"
        : "+f"(d[0]), "+f"(d[1]), "+f"(d[2]), "+f"(d[3])
        : "r"(a[0]), "r"(a[1]), "r"(a[2]), "r"(a[3]), "r"(b[0]), "r"(b[1]));
}

// ---------------------------------------------------------------------------
// Fused split: all 6 fp32 tensors -> (hi, lo) bf16 pairs, one launch.
// ---------------------------------------------------------------------------
__global__ __launch_bounds__(256) void split_all(
    const float4* __restrict__ x, const float4* __restrict__ xkv,
    const float4* __restrict__ wq, const float4* __restrict__ wk,
    const float4* __restrict__ wv, const float4* __restrict__ wp,
    __nv_bfloat162* __restrict__ xhi, __nv_bfloat162* __restrict__ xlo,
    __nv_bfloat162* __restrict__ kvhi, __nv_bfloat162* __restrict__ kvlo,
    __nv_bfloat162* __restrict__ whi, __nv_bfloat162* __restrict__ wlo) {
    int blk = blockIdx.x;
    const float4* src;
    __nv_bfloat162 *ho, *lo_;
    int idx;
    if (blk < 1568) {
        src = x; ho = xhi; lo_ = xlo; idx = blk;
    } else if (blk < 3136) {
        src = xkv; ho = kvhi; lo_ = kvlo; idx = blk - 1568;
    } else {
        int w = (blk - 3136) >> 6;
        idx = (blk - 3136) & 63;
        src = (w == 0) ? wq : (w == 1) ? wk : (w == 2) ? wv : wp;
        ho = whi + w * 32768;
        lo_ = wlo + w * 32768;
    }
    int i = idx * 256 + threadIdx.x;
    float4 v = src[i];
    __nv_bfloat16 h0 = __float2bfloat16(v.x), h1 = __float2bfloat16(v.y);
    __nv_bfloat16 h2 = __float2bfloat16(v.z), h3 = __float2bfloat16(v.w);
    ho[2 * i + 0] = __nv_bfloat162(h0, h1);
    ho[2 * i + 1] = __nv_bfloat162(h2, h3);
    lo_[2 * i + 0] = __nv_bfloat162(__float2bfloat16(v.x - __bfloat162float(h0)),
                                    __float2bfloat16(v.y - __bfloat162float(h1)));
    lo_[2 * i + 1] = __nv_bfloat162(__float2bfloat16(v.z - __bfloat162float(h2)),
                                    __float2bfloat16(v.w - __bfloat162float(h3)));
}

// ---------------------------------------------------------------------------
// HMMA GEMM body: out[64x64 tile] = Ahi@Whi^T + Ahi@Wlo^T + Alo@Whi^T (+bias)
// 256 threads = 8 warps, warp grid 4m x 2n, warp tile 16x32.
// 3-stage depth-2 cp.async pipeline, one __syncthreads per K-chunk.
// Smem rows padded to 40 bf16 (80B) -> conflict-free ldmatrix.
// Stage = 4 mats x 64 rows x 80B = 20480B; 3 stages -> 3 CTAs/SM (24 warps).
// ---------------------------------------------------------------------------
#define SM_MAT   5120          // 64 * 40 * 2
#define SM_STAGE 20480         // 4 * SM_MAT
#define N_STAGE  3
#define SMEM_BYTES (N_STAGE * SM_STAGE + 256)

__device__ __forceinline__ void gemm_body(const __nv_bfloat16* __restrict__ Ahi,
                                          const __nv_bfloat16* __restrict__ Alo,
                                          const __nv_bfloat16* __restrict__ Whi,
                                          const __nv_bfloat16* __restrict__ Wlo,
                                          float* __restrict__ out,
                                          const float* __restrict__ bias,
                                          int m0, int n0, char* sm) {
    uint32_t smu = smem_u32(sm);
    float* bsm = (float*)(sm + N_STAGE * SM_STAGE);

    const int tid = threadIdx.x;
    const int wid = tid >> 5, lane = tid & 31;
    const int wm = (wid & 3) * 16, wn = (wid >> 2) * 32;

    if (tid < 64) bsm[tid] = bias ? bias[n0 + tid] : 0.0f;

    const __nv_bfloat16* aH = Ahi + (size_t)m0 * Cc;
    const __nv_bfloat16* aL = Alo + (size_t)m0 * Cc;
    const __nv_bfloat16* wH = Whi + (size_t)n0 * Cc;
    const __nv_bfloat16* wL = Wlo + (size_t)n0 * Cc;

    const int lrow = tid >> 2, lj = tid & 3;  // 64 rows x 4 vec16 per mat

    auto load_chunk = [&](int s, int c) {
        int k0 = c * 32;
        uint32_t sb = smu + s * SM_STAGE + lrow * 80 + lj * 16;
        size_t go = (size_t)lrow * Cc + k0 + lj * 8;
        cp_async16(sb,              aH + go);
        cp_async16(sb + SM_MAT,     aL + go);
        cp_async16(sb + 2 * SM_MAT, wH + go);
        cp_async16(sb + 3 * SM_MAT, wL + go);
        cp_commit();
    };

    float acc[4][4];
#pragma unroll
    for (int a = 0; a < 4; a++)
#pragma unroll
        for (int b = 0; b < 4; b++) acc[a][b] = 0.0f;

    load_chunk(0, 0);
    load_chunk(1, 1);

    const int r = lane & 15, kh = lane >> 4;

    for (int c = 0; c < 8; c++) {
        if (c < 7) cp_wait1();
        else       cp_wait0();
        __syncthreads();
        if (c + 2 < 8) load_chunk((c + 2) % N_STAGE, c + 2);

        int cur = c % N_STAGE;
        uint32_t sAH = smu + cur * SM_STAGE;
        uint32_t sAL = sAH + SM_MAT;
        uint32_t sWH = sAH + 2 * SM_MAT;
        uint32_t sWL = sAH + 3 * SM_MAT;

#pragma unroll
        for (int ks = 0; ks < 2; ks++) {
            int kcol = ks * 16 + kh * 8;
            uint32_t AH[4], AL[4], BH[4][2], BL[4][2];
            {
                uint32_t off = (uint32_t)((wm + r) * 40 + kcol) * 2;
                ldsm4(AH, sAH + off);
                ldsm4(AL, sAL + off);
            }
#pragma unroll
            for (int nj = 0; nj < 2; nj++) {
                uint32_t off = (uint32_t)((wn + nj * 16 + r) * 40 + kcol) * 2;
                uint32_t th[4], tl[4];
                ldsm4(th, sWH + off);
                ldsm4(tl, sWL + off);
                BH[nj * 2 + 0][0] = th[0]; BH[nj * 2 + 0][1] = th[2];
                BH[nj * 2 + 1][0] = th[1]; BH[nj * 2 + 1][1] = th[3];
                BL[nj * 2 + 0][0] = tl[0]; BL[nj * 2 + 0][1] = tl[2];
                BL[nj * 2 + 1][0] = tl[1]; BL[nj * 2 + 1][1] = tl[3];
            }
#pragma unroll
            for (int ni = 0; ni < 4; ni++) {
                mma16816(acc[ni], AH, BH[ni]);
                mma16816(acc[ni], AH, BL[ni]);
                mma16816(acc[ni], AL, BH[ni]);
            }
        }
    }

    const int g = lane >> 2, tg = lane & 3;
#pragma unroll
    for (int ni = 0; ni < 4; ni++) {
        int row = m0 + wm + g;
        int coll = wn + ni * 8 + tg * 2;
        int col = n0 + coll;
        float2 v0 = make_float2(acc[ni][0] + bsm[coll], acc[ni][1] + bsm[coll + 1]);
        float2 v1 = make_float2(acc[ni][2] + bsm[coll], acc[ni][3] + bsm[coll + 1]);
        *(float2*)(out + (size_t)row * Cc + col) = v0;
        *(float2*)(out + (size_t)(row + 8) * Cc + col) = v1;
    }
}

// Fused Q/K/V projections: grid (98, 4, 3); z selects {x@Wq, xkv@Wk, xkv@Wv}.
__global__ __launch_bounds__(256) void gemm_qkv(
    const __nv_bfloat16* __restrict__ xhi, const __nv_bfloat16* __restrict__ xlo,
    const __nv_bfloat16* __restrict__ kvhi, const __nv_bfloat16* __restrict__ kvlo,
    const __nv_bfloat16* __restrict__ whi, const __nv_bfloat16* __restrict__ wlo,
    float* __restrict__ Q, float* __restrict__ K, float* __restrict__ V) {
    extern __shared__ char sm[];
    int z = blockIdx.z;
    const __nv_bfloat16* Ahi = (z == 0) ? xhi : kvhi;
    const __nv_bfloat16* Alo = (z == 0) ? xlo : kvlo;
    const __nv_bfloat16* Wh = whi + (size_t)z * 65536;
    const __nv_bfloat16* Wl = wlo + (size_t)z * 65536;
    float* out = (z == 0) ? Q : (z == 1) ? K : V;
    gemm_body(Ahi, Alo, Wh, Wl, out, nullptr, blockIdx.x * 64, blockIdx.y * 64, sm);
}

// Output projection (with bias).
__global__ __launch_bounds__(256) void gemm_out(
    const __nv_bfloat16* __restrict__ Ahi, const __nv_bfloat16* __restrict__ Alo,
    const __nv_bfloat16* __restrict__ Whi, const __nv_bfloat16* __restrict__ Wlo,
    float* __restrict__ out, const float* __restrict__ bias) {
    extern __shared__ char sm[];
    gemm_body(Ahi, Alo, Whi, Wlo, out, bias, blockIdx.x * 64, blockIdx.y * 64, sm);
}

// ---------------------------------------------------------------------------
// Local windowed attention (radius 3 -> 29 neighbors).
// 4 queries per block; 64 threads per query; each thread owns 4 channels.
// Head = group of 8 lanes -> 3-shuffle dot reduction. Two-pass softmax.
// ---------------------------------------------------------------------------
struct alignas(8) bf16x4 { __nv_bfloat162 a, b; };

__global__ __launch_bounds__(256) void local_attn(const float* __restrict__ Q,
                                                  const float* __restrict__ K,
                                                  const float* __restrict__ V,
                                                  __nv_bfloat16* __restrict__ Ohi,
                                                  __nv_bfloat16* __restrict__ Olo) {
    int slot = threadIdx.x >> 6;
    int t = threadIdx.x & 63;
    int bn = blockIdx.x * 4 + slot;
    int b = bn / Nn;
    int n = bn - b * Nn;
    int yy = n / Hh;
    int xx = n - yy * Hh;

    const float scale = 0.17677669529663687f;  // 32^-0.5
    size_t qoff = (size_t)bn * Cc + t * 4;
    float4 q4 = *(const float4*)(Q + qoff);
    q4.x *= scale; q4.y *= scale; q4.z *= scale; q4.w *= scale;

    const int dy[29] = {-3,-2,-2,-2,-2,-2,-1,-1,-1,-1,-1, 0, 0, 0, 0, 0, 0, 0,
                         1, 1, 1, 1, 1, 2, 2, 2, 2, 2, 3};
    const int dx[29] = { 0,-2,-1, 0, 1, 2,-2,-1, 0, 1, 2,-3,-2,-1, 0, 1, 2, 3,
                        -2,-1, 0, 1, 2,-2,-1, 0, 1, 2, 0};

    size_t base = (size_t)b * Nn;
    int off[29];
    float sc[29];
    float m = -1e30f;
#pragma unroll
    for (int i = 0; i < 29; i++) {
        int ny = yy + dy[i], nx = xx + dx[i];
        bool ok = ((unsigned)ny < (unsigned)Hh) && ((unsigned)nx < (unsigned)Hh);
        int nn = ok ? ny * Hh + nx : n;
        off[i] = nn;
        const float4 k4 = *(const float4*)(K + (base + nn) * Cc + t * 4);
        float p = q4.x * k4.x + q4.y * k4.y + q4.z * k4.z + q4.w * k4.w;
        p += __shfl_xor_sync(0xffffffffu, p, 1);
        p += __shfl_xor_sync(0xffffffffu, p, 2);
        p += __shfl_xor_sync(0xffffffffu, p, 4);
        sc[i] = ok ? p : -1e30f;
        m = fmaxf(m, sc[i]);
    }

    float s = 0.f;
    float4 acc = make_float4(0.f, 0.f, 0.f, 0.f);
#pragma unroll
    for (int i = 0; i < 29; i++) {
        float e = __expf(sc[i] - m);
        s += e;
        const float4 v4 = *(const float4*)(V + (base + off[i]) * Cc + t * 4);
        acc.x = fmaf(e, v4.x, acc.x);
        acc.y = fmaf(e, v4.y, acc.y);
        acc.z = fmaf(e, v4.z, acc.z);
        acc.w = fmaf(e, v4.w, acc.w);
    }
    float inv = __fdividef(1.0f, s);
    float4 o = make_float4(acc.x * inv, acc.y * inv, acc.z * inv, acc.w * inv);

    __nv_bfloat16 h0 = __float2bfloat16(o.x), h1 = __float2bfloat16(o.y);
    __nv_bfloat16 h2 = __float2bfloat16(o.z), h3 = __float2bfloat16(o.w);
    bf16x4 hv, lv;
    hv.a = __nv_bfloat162(h0, h1);
    hv.b = __nv_bfloat162(h2, h3);
    lv.a = __nv_bfloat162(__float2bfloat16(o.x - __bfloat162float(h0)),
                          __float2bfloat16(o.y - __bfloat162float(h1)));
    lv.b = __nv_bfloat162(__float2bfloat16(o.z - __bfloat162float(h2)),
                          __float2bfloat16(o.w - __bfloat162float(h3)));
    *(bf16x4*)(Ohi + qoff) = hv;
    *(bf16x4*)(Olo + qoff) = lv;
}

// ---------------------------------------------------------------------------
extern "C" void kernel_launch(void* const* d_in, const int* in_sizes, int n_in,
                              void* d_out, int out_size) {
    const float* x   = (const float*)d_in[0];
    const float* xkv = (const float*)d_in[1];
    const float* Wq  = (const float*)d_in[2];
    const float* Wk  = (const float*)d_in[3];
    const float* Wv  = (const float*)d_in[4];
    const float* Wp  = (const float*)d_in[5];
    const float* bp  = (const float*)d_in[6];
    float* out = (float*)d_out;

    float *Qp, *Kp, *Vp;
    __nv_bfloat16 *xhi, *xlo, *kvhi, *kvlo, *ahi, *alo, *whi, *wlo;
    cudaGetSymbolAddress((void**)&Qp, g_Q);
    cudaGetSymbolAddress((void**)&Kp, g_K);
    cudaGetSymbolAddress((void**)&Vp, g_V);
    cudaGetSymbolAddress((void**)&xhi, g_xhi);
    cudaGetSymbolAddress((void**)&xlo, g_xlo);
    cudaGetSymbolAddress((void**)&kvhi, g_kvhi);
    cudaGetSymbolAddress((void**)&kvlo, g_kvlo);
    cudaGetSymbolAddress((void**)&ahi, g_ahi);
    cudaGetSymbolAddress((void**)&alo, g_alo);
    cudaGetSymbolAddress((void**)&whi, g_whi);
    cudaGetSymbolAddress((void**)&wlo, g_wlo);

    cudaFuncSetAttribute(gemm_qkv, cudaFuncAttributeMaxDynamicSharedMemorySize, SMEM_BYTES);
    cudaFuncSetAttribute(gemm_out, cudaFuncAttributeMaxDynamicSharedMemorySize, SMEM_BYTES);

    split_all<<<3392, 256>>>((const float4*)x, (const float4*)xkv,
                             (const float4*)Wq, (const float4*)Wk,
                             (const float4*)Wv, (const float4*)Wp,
                             (__nv_bfloat162*)xhi, (__nv_bfloat162*)xlo,
                             (__nv_bfloat162*)kvhi, (__nv_bfloat162*)kvlo,
                             (__nv_bfloat162*)whi, (__nv_bfloat162*)wlo);

    dim3 gqkv(Mtot / 64, Cc / 64, 3);   // (98, 4, 3) = 1176 CTAs
    gemm_qkv<<<gqkv, 256, SMEM_BYTES>>>(xhi, xlo, kvhi, kvlo, whi, wlo, Qp, Kp, Vp);

    local_attn<<<Mtot / 4, 256>>>(Qp, Kp, Vp, ahi, alo);

    dim3 gout(Mtot / 64, Cc / 64);      // (98, 4) = 392 CTAs
    gemm_out<<<gout, 256, SMEM_BYTES>>>(ahi, alo, whi + 196608, wlo + 196608, out, bp);
}

// round 7
// speedup vs baseline: 2.1184x; 1.0155x over previous
#include <cuda_runtime.h>
#include <cuda_bf16.h>
#include <cstdint>

#define Bb 2
#define Nn 3136
#define Cc 256
#define Hh 56
#define Mtot (Bb * Nn)   // 6272

// ---------------- scratch (allocation-free) ----------------
__device__ float g_Q[Mtot * Cc];
__device__ float g_K[Mtot * Cc];
__device__ float g_V[Mtot * Cc];
__device__ __nv_bfloat16 g_xhi[Mtot * Cc], g_xlo[Mtot * Cc];
__device__ __nv_bfloat16 g_kvhi[Mtot * Cc], g_kvlo[Mtot * Cc];
__device__ __nv_bfloat16 g_ahi[Mtot * Cc], g_alo[Mtot * Cc];
__device__ __nv_bfloat16 g_whi[4 * Cc * Cc], g_wlo[4 * Cc * Cc];

// ---------------- portable (sm_80+) PTX helpers ----------------
__device__ __forceinline__ uint32_t smem_u32(const void* p) {
    uint32_t a;
    asm("{ .reg .u64 t; cvta.to.shared.u64 t, %1; cvt.u32.u64 %0, t; }" : "=r"(a) : "l"(p));
    return a;
}
__device__ __forceinline__ void cp_async16(uint32_t dst, const void* src) {
    asm volatile("cp.async.cg.shared.global [%0], [%1], 16;" :: "r"(dst), "l"(src) : "memory");
}
__device__ __forceinline__ void cp_commit() { asm volatile("cp.async.commit_group;" ::: "memory"); }
__device__ __forceinline__ void cp_wait1() { asm volatile("cp.async.wait_group 1;" ::: "memory"); }
__device__ __forceinline__ void cp_wait0() { asm volatile("cp.async.wait_group 0;" ::: "memory"); }
__device__ __forceinline__ void ldsm4(uint32_t* r, uint32_t addr) {
    asm volatile("ldmatrix.sync.aligned.m8n8.x4.shared.b16 {%0,%1,%2,%3}, [%4];"
                 : "=r"(r[0]), "=r"(r[1]), "=r"(r[2]), "=r"(r[3]) : "r"(addr));
}
__device__ __forceinline__ void mma16816(float* d, const uint32_t* a, const uint32_t* b) {
    asm volatile(
        "mma.sync.aligned.m16n8k16.row.col.f32.bf16.bf16.f32 "
        "{%0,%1,%2,%3}, {%4,%5,%6,%7}, {%8,%9}, {%0,%1,%2,%3};"
        : "+f"(d[0]), "+f"(d[1]), "+f"(d[2]), "+f"(d[3])
        : "r"(a[0]), "r"(a[1]), "r"(a[2]), "r"(a[3]), "r"(b[0]), "r"(b[1]));
}

// ---------------------------------------------------------------------------
// Fused split: all 6 fp32 tensors -> (hi, lo) bf16 pairs, one launch.
// ---------------------------------------------------------------------------
__global__ __launch_bounds__(256) void split_all(
    const float4* __restrict__ x, const float4* __restrict__ xkv,
    const float4* __restrict__ wq, const float4* __restrict__ wk,
    const float4* __restrict__ wv, const float4* __restrict__ wp,
    __nv_bfloat162* __restrict__ xhi, __nv_bfloat162* __restrict__ xlo,
    __nv_bfloat162* __restrict__ kvhi, __nv_bfloat162* __restrict__ kvlo,
    __nv_bfloat162* __restrict__ whi, __nv_bfloat162* __restrict__ wlo) {
    int blk = blockIdx.x;
    const float4* src;
    __nv_bfloat162 *ho, *lo_;
    int idx;
    if (blk < 1568) {
        src = x; ho = xhi; lo_ = xlo; idx = blk;
    } else if (blk < 3136) {
        src = xkv; ho = kvhi; lo_ = kvlo; idx = blk - 1568;
    } else {
        int w = (blk - 3136) >> 6;
        idx = (blk - 3136) & 63;
        src = (w == 0) ? wq : (w == 1) ? wk : (w == 2) ? wv : wp;
        ho = whi + w * 32768;
        lo_ = wlo + w * 32768;
    }
    int i = idx * 256 + threadIdx.x;
    float4 v = src[i];
    __nv_bfloat16 h0 = __float2bfloat16(v.x), h1 = __float2bfloat16(v.y);
    __nv_bfloat16 h2 = __float2bfloat16(v.z), h3 = __float2bfloat16(v.w);
    ho[2 * i + 0] = __nv_bfloat162(h0, h1);
    ho[2 * i + 1] = __nv_bfloat162(h2, h3);
    lo_[2 * i + 0] = __nv_bfloat162(__float2bfloat16(v.x - __bfloat162float(h0)),
                                    __float2bfloat16(v.y - __bfloat162float(h1)));
    lo_[2 * i + 1] = __nv_bfloat162(__float2bfloat16(v.z - __bfloat162float(h2)),
                                    __float2bfloat16(v.w - __bfloat162float(h3)));
}

// ---------------------------------------------------------------------------
// HMMA GEMM body: out[64x64 tile] = Ahi@Whi^T + Ahi@Wlo^T + Alo@Whi^T (+bias)
// 256 threads = 8 warps, warp grid 4m x 2n, warp tile 16x32.
// SPLIT ACCUMULATORS: main term (AH*BH) -> accA, corrections -> accB.
// Doubles independent HMMA chains per warp (4 -> 8) to hide MMA latency.
// 3-stage depth-2 cp.async pipeline, one __syncthreads per K-chunk.
// ---------------------------------------------------------------------------
#define SM_MAT   5120          // 64 * 40 * 2
#define SM_STAGE 20480         // 4 * SM_MAT
#define N_STAGE  3
#define SMEM_BYTES (N_STAGE * SM_STAGE + 256)

__device__ __forceinline__ void gemm_body(const __nv_bfloat16* __restrict__ Ahi,
                                          const __nv_bfloat16* __restrict__ Alo,
                                          const __nv_bfloat16* __restrict__ Whi,
                                          const __nv_bfloat16* __restrict__ Wlo,
                                          float* __restrict__ out,
                                          const float* __restrict__ bias,
                                          int m0, int n0, char* sm) {
    uint32_t smu = smem_u32(sm);
    float* bsm = (float*)(sm + N_STAGE * SM_STAGE);

    const int tid = threadIdx.x;
    const int wid = tid >> 5, lane = tid & 31;
    const int wm = (wid & 3) * 16, wn = (wid >> 2) * 32;

    if (tid < 64) bsm[tid] = bias ? bias[n0 + tid] : 0.0f;

    const __nv_bfloat16* aH = Ahi + (size_t)m0 * Cc;
    const __nv_bfloat16* aL = Alo + (size_t)m0 * Cc;
    const __nv_bfloat16* wH = Whi + (size_t)n0 * Cc;
    const __nv_bfloat16* wL = Wlo + (size_t)n0 * Cc;

    const int lrow = tid >> 2, lj = tid & 3;  // 64 rows x 4 vec16 per mat

    auto load_chunk = [&](int s, int c) {
        int k0 = c * 32;
        uint32_t sb = smu + s * SM_STAGE + lrow * 80 + lj * 16;
        size_t go = (size_t)lrow * Cc + k0 + lj * 8;
        cp_async16(sb,              aH + go);
        cp_async16(sb + SM_MAT,     aL + go);
        cp_async16(sb + 2 * SM_MAT, wH + go);
        cp_async16(sb + 3 * SM_MAT, wL + go);
        cp_commit();
    };

    float accA[4][4], accB[4][4];
#pragma unroll
    for (int a = 0; a < 4; a++)
#pragma unroll
        for (int b = 0; b < 4; b++) { accA[a][b] = 0.0f; accB[a][b] = 0.0f; }

    load_chunk(0, 0);
    load_chunk(1, 1);

    const int r = lane & 15, kh = lane >> 4;

    for (int c = 0; c < 8; c++) {
        if (c < 7) cp_wait1();
        else       cp_wait0();
        __syncthreads();
        if (c + 2 < 8) load_chunk((c + 2) % N_STAGE, c + 2);

        int cur = c % N_STAGE;
        uint32_t sAH = smu + cur * SM_STAGE;
        uint32_t sAL = sAH + SM_MAT;
        uint32_t sWH = sAH + 2 * SM_MAT;
        uint32_t sWL = sAH + 3 * SM_MAT;

#pragma unroll
        for (int ks = 0; ks < 2; ks++) {
            int kcol = ks * 16 + kh * 8;
            uint32_t AH[4], AL[4], BH[4][2], BL[4][2];
            {
                uint32_t off = (uint32_t)((wm + r) * 40 + kcol) * 2;
                ldsm4(AH, sAH + off);
                ldsm4(AL, sAL + off);
            }
#pragma unroll
            for (int nj = 0; nj < 2; nj++) {
                uint32_t off = (uint32_t)((wn + nj * 16 + r) * 40 + kcol) * 2;
                uint32_t th[4], tl[4];
                ldsm4(th, sWH + off);
                ldsm4(tl, sWL + off);
                BH[nj * 2 + 0][0] = th[0]; BH[nj * 2 + 0][1] = th[2];
                BH[nj * 2 + 1][0] = th[1]; BH[nj * 2 + 1][1] = th[3];
                BL[nj * 2 + 0][0] = tl[0]; BL[nj * 2 + 0][1] = tl[2];
                BL[nj * 2 + 1][0] = tl[1]; BL[nj * 2 + 1][1] = tl[3];
            }
            // 8 independent accumulation streams: accA[ni] (1 MMA) + accB[ni] (2 MMAs)
#pragma unroll
            for (int ni = 0; ni < 4; ni++) mma16816(accA[ni], AH, BH[ni]);
#pragma unroll
            for (int ni = 0; ni < 4; ni++) mma16816(accB[ni], AH, BL[ni]);
#pragma unroll
            for (int ni = 0; ni < 4; ni++) mma16816(accB[ni], AL, BH[ni]);
        }
    }

    const int g = lane >> 2, tg = lane & 3;
#pragma unroll
    for (int ni = 0; ni < 4; ni++) {
        int row = m0 + wm + g;
        int coll = wn + ni * 8 + tg * 2;
        int col = n0 + coll;
        float2 v0 = make_float2(accA[ni][0] + accB[ni][0] + bsm[coll],
                                accA[ni][1] + accB[ni][1] + bsm[coll + 1]);
        float2 v1 = make_float2(accA[ni][2] + accB[ni][2] + bsm[coll],
                                accA[ni][3] + accB[ni][3] + bsm[coll + 1]);
        *(float2*)(out + (size_t)row * Cc + col) = v0;
        *(float2*)(out + (size_t)(row + 8) * Cc + col) = v1;
    }
}

// Fused Q/K/V projections: grid (98, 4, 3); z selects {x@Wq, xkv@Wk, xkv@Wv}.
__global__ __launch_bounds__(256, 3) void gemm_qkv(
    const __nv_bfloat16* __restrict__ xhi, const __nv_bfloat16* __restrict__ xlo,
    const __nv_bfloat16* __restrict__ kvhi, const __nv_bfloat16* __restrict__ kvlo,
    const __nv_bfloat16* __restrict__ whi, const __nv_bfloat16* __restrict__ wlo,
    float* __restrict__ Q, float* __restrict__ K, float* __restrict__ V) {
    extern __shared__ char sm[];
    int z = blockIdx.z;
    const __nv_bfloat16* Ahi = (z == 0) ? xhi : kvhi;
    const __nv_bfloat16* Alo = (z == 0) ? xlo : kvlo;
    const __nv_bfloat16* Wh = whi + (size_t)z * 65536;
    const __nv_bfloat16* Wl = wlo + (size_t)z * 65536;
    float* out = (z == 0) ? Q : (z == 1) ? K : V;
    gemm_body(Ahi, Alo, Wh, Wl, out, nullptr, blockIdx.x * 64, blockIdx.y * 64, sm);
}

// Output projection (with bias).
__global__ __launch_bounds__(256, 3) void gemm_out(
    const __nv_bfloat16* __restrict__ Ahi, const __nv_bfloat16* __restrict__ Alo,
    const __nv_bfloat16* __restrict__ Whi, const __nv_bfloat16* __restrict__ Wlo,
    float* __restrict__ out, const float* __restrict__ bias) {
    extern __shared__ char sm[];
    gemm_body(Ahi, Alo, Whi, Wlo, out, bias, blockIdx.x * 64, blockIdx.y * 64, sm);
}

// ---------------------------------------------------------------------------
// Local windowed attention (radius 3 -> 29 neighbors).
// 4 queries per block; 64 threads per query; each thread owns 4 channels.
// Head = group of 8 lanes -> 3-shuffle dot reduction. Two-pass softmax.
// ---------------------------------------------------------------------------
struct alignas(8) bf16x4 { __nv_bfloat162 a, b; };

__global__ __launch_bounds__(256) void local_attn(const float* __restrict__ Q,
                                                  const float* __restrict__ K,
                                                  const float* __restrict__ V,
                                                  __nv_bfloat16* __restrict__ Ohi,
                                                  __nv_bfloat16* __restrict__ Olo) {
    int slot = threadIdx.x >> 6;
    int t = threadIdx.x & 63;
    int bn = blockIdx.x * 4 + slot;
    int b = bn / Nn;
    int n = bn - b * Nn;
    int yy = n / Hh;
    int xx = n - yy * Hh;

    const float scale = 0.17677669529663687f;  // 32^-0.5
    size_t qoff = (size_t)bn * Cc + t * 4;
    float4 q4 = *(const float4*)(Q + qoff);
    q4.x *= scale; q4.y *= scale; q4.z *= scale; q4.w *= scale;

    const int dy[29] = {-3,-2,-2,-2,-2,-2,-1,-1,-1,-1,-1, 0, 0, 0, 0, 0, 0, 0,
                         1, 1, 1, 1, 1, 2, 2, 2, 2, 2, 3};
    const int dx[29] = { 0,-2,-1, 0, 1, 2,-2,-1, 0, 1, 2,-3,-2,-1, 0, 1, 2, 3,
                        -2,-1, 0, 1, 2,-2,-1, 0, 1, 2, 0};

    size_t base = (size_t)b * Nn;
    int off[29];
    float sc[29];
    float m = -1e30f;
#pragma unroll
    for (int i = 0; i < 29; i++) {
        int ny = yy + dy[i], nx = xx + dx[i];
        bool ok = ((unsigned)ny < (unsigned)Hh) && ((unsigned)nx < (unsigned)Hh);
        int nn = ok ? ny * Hh + nx : n;
        off[i] = nn;
        const float4 k4 = *(const float4*)(K + (base + nn) * Cc + t * 4);
        float p = q4.x * k4.x + q4.y * k4.y + q4.z * k4.z + q4.w * k4.w;
        p += __shfl_xor_sync(0xffffffffu, p, 1);
        p += __shfl_xor_sync(0xffffffffu, p, 2);
        p += __shfl_xor_sync(0xffffffffu, p, 4);
        sc[i] = ok ? p : -1e30f;
        m = fmaxf(m, sc[i]);
    }

    float s = 0.f;
    float4 acc = make_float4(0.f, 0.f, 0.f, 0.f);
#pragma unroll
    for (int i = 0; i < 29; i++) {
        float e = __expf(sc[i] - m);
        s += e;
        const float4 v4 = *(const float4*)(V + (base + off[i]) * Cc + t * 4);
        acc.x = fmaf(e, v4.x, acc.x);
        acc.y = fmaf(e, v4.y, acc.y);
        acc.z = fmaf(e, v4.z, acc.z);
        acc.w = fmaf(e, v4.w, acc.w);
    }
    float inv = __fdividef(1.0f, s);
    float4 o = make_float4(acc.x * inv, acc.y * inv, acc.z * inv, acc.w * inv);

    __nv_bfloat16 h0 = __float2bfloat16(o.x), h1 = __float2bfloat16(o.y);
    __nv_bfloat16 h2 = __float2bfloat16(o.z), h3 = __float2bfloat16(o.w);
    bf16x4 hv, lv;
    hv.a = __nv_bfloat162(h0, h1);
    hv.b = __nv_bfloat162(h2, h3);
    lv.a = __nv_bfloat162(__float2bfloat16(o.x - __bfloat162float(h0)),
                          __float2bfloat16(o.y - __bfloat162float(h1)));
    lv.b = __nv_bfloat162(__float2bfloat16(o.z - __bfloat162float(h2)),
                          __float2bfloat16(o.w - __bfloat162float(h3)));
    *(bf16x4*)(Ohi + qoff) = hv;
    *(bf16x4*)(Olo + qoff) = lv;
}

// ---------------------------------------------------------------------------
extern "C" void kernel_launch(void* const* d_in, const int* in_sizes, int n_in,
                              void* d_out, int out_size) {
    const float* x   = (const float*)d_in[0];
    const float* xkv = (const float*)d_in[1];
    const float* Wq  = (const float*)d_in[2];
    const float* Wk  = (const float*)d_in[3];
    const float* Wv  = (const float*)d_in[4];
    const float* Wp  = (const float*)d_in[5];
    const float* bp  = (const float*)d_in[6];
    float* out = (float*)d_out;

    float *Qp, *Kp, *Vp;
    __nv_bfloat16 *xhi, *xlo, *kvhi, *kvlo, *ahi, *alo, *whi, *wlo;
    cudaGetSymbolAddress((void**)&Qp, g_Q);
    cudaGetSymbolAddress((void**)&Kp, g_K);
    cudaGetSymbolAddress((void**)&Vp, g_V);
    cudaGetSymbolAddress((void**)&xhi, g_xhi);
    cudaGetSymbolAddress((void**)&xlo, g_xlo);
    cudaGetSymbolAddress((void**)&kvhi, g_kvhi);
    cudaGetSymbolAddress((void**)&kvlo, g_kvlo);
    cudaGetSymbolAddress((void**)&ahi, g_ahi);
    cudaGetSymbolAddress((void**)&alo, g_alo);
    cudaGetSymbolAddress((void**)&whi, g_whi);
    cudaGetSymbolAddress((void**)&wlo, g_wlo);

    cudaFuncSetAttribute(gemm_qkv, cudaFuncAttributeMaxDynamicSharedMemorySize, SMEM_BYTES);
    cudaFuncSetAttribute(gemm_out, cudaFuncAttributeMaxDynamicSharedMemorySize, SMEM_BYTES);

    split_all<<<3392, 256>>>((const float4*)x, (const float4*)xkv,
                             (const float4*)Wq, (const float4*)Wk,
                             (const float4*)Wv, (const float4*)Wp,
                             (__nv_bfloat162*)xhi, (__nv_bfloat162*)xlo,
                             (__nv_bfloat162*)kvhi, (__nv_bfloat162*)kvlo,
                             (__nv_bfloat162*)whi, (__nv_bfloat162*)wlo);

    dim3 gqkv(Mtot / 64, Cc / 64, 3);   // (98, 4, 3) = 1176 CTAs
    gemm_qkv<<<gqkv, 256, SMEM_BYTES>>>(xhi, xlo, kvhi, kvlo, whi, wlo, Qp, Kp, Vp);

    local_attn<<<Mtot / 4, 256>>>(Qp, Kp, Vp, ahi, alo);

    dim3 gout(Mtot / 64, Cc / 64);      // (98, 4) = 392 CTAs
    gemm_out<<<gout, 256, SMEM_BYTES>>>(ahi, alo, whi + 196608, wlo + 196608, out, bp);
}